// round 4
// baseline (speedup 1.0000x reference)
#include <cuda_runtime.h>
#include <cuda_bf16.h>
#include <math.h>
#include <stdint.h>

#define T_TOK 1024
#define HDIM  1024
#define IDIM  512
#define NEXP  64
#define TOPK  8

// ================= scratch (static device globals; no allocation) =================
__device__ int   g_count[NEXP];
__device__ int   g_assign_tok[NEXP * T_TOK];
__device__ float g_assign_w[NEXP * T_TOK];
__device__ int   g_tok2slot[T_TOK * TOPK];
__device__ __nv_bfloat16 g_xhi[T_TOK * HDIM];
__device__ __nv_bfloat16 g_xlo[T_TOK * HDIM];
__device__ __nv_bfloat16 g_sact_hi[T_TOK * IDIM];
__device__ __nv_bfloat16 g_sact_lo[T_TOK * IDIM];
__device__ __nv_bfloat16 g_act_hi[(size_t)NEXP * T_TOK * IDIM];
__device__ __nv_bfloat16 g_act_lo[(size_t)NEXP * T_TOK * IDIM];
__device__ float g_part[(size_t)NEXP * T_TOK * HDIM];

// ================= primitives =================
__device__ __forceinline__ uint32_t smem_u32(const void* p) {
    uint32_t a;
    asm("{ .reg .u64 t; cvta.to.shared.u64 t, %1; cvt.u32.u64 %0, t; }" : "=r"(a) : "l"(p));
    return a;
}
__device__ __forceinline__ void ldsm4(uint32_t* r, uint32_t a) {
    asm volatile("ldmatrix.sync.aligned.m8n8.x4.shared.b16 {%0,%1,%2,%3}, [%4];"
                 : "=r"(r[0]), "=r"(r[1]), "=r"(r[2]), "=r"(r[3]) : "r"(a));
}
__device__ __forceinline__ void ldsm2t(uint32_t* r, uint32_t a) {
    asm volatile("ldmatrix.sync.aligned.m8n8.x2.trans.shared.b16 {%0,%1}, [%2];"
                 : "=r"(r[0]), "=r"(r[1]) : "r"(a));
}
__device__ __forceinline__ void mma16816(float* c, const uint32_t* a, const uint32_t* b) {
    asm volatile(
        "mma.sync.aligned.m16n8k16.row.col.f32.bf16.bf16.f32 "
        "{%0,%1,%2,%3}, {%4,%5,%6,%7}, {%8,%9}, {%0,%1,%2,%3};"
        : "+f"(c[0]), "+f"(c[1]), "+f"(c[2]), "+f"(c[3])
        : "r"(a[0]), "r"(a[1]), "r"(a[2]), "r"(a[3]), "r"(b[0]), "r"(b[1]));
}
__device__ __forceinline__ void cpa16(uint32_t dst, const void* src) {
    asm volatile("cp.async.cg.shared.global [%0], [%1], 16;" :: "r"(dst), "l"(src));
}
#define CP_COMMIT() asm volatile("cp.async.commit_group;" ::: "memory")
#define CP_WAIT0()  asm volatile("cp.async.wait_group 0;"  ::: "memory")

// ================= layout =================
#define A_PITCH 80
#define B_PITCH 144
#define A_BYTES (128 * A_PITCH)                 // 10240
#define B_BYTES (32 * B_PITCH)                  // 4608
#define GU_STG  (2 * A_BYTES + 4 * B_BYTES)     // 38912
#define DN_STG  (2 * A_BYTES + 2 * B_BYTES)     // 29696
#define GU_SMEM (2 * GU_STG + 2 * 8192)         // 94208
#define DN_SMEM (2 * DN_STG + 8192)             // 67584

// convert 8 staged fp32 -> bf16 hi/lo rows in smem
__device__ __forceinline__ void convB(const char* stg, char* bh, char* bl, int br, int bc8) {
    const float4 w0 = *(const float4*)(stg + br * 256 + bc8 * 4);
    const float4 w1 = *(const float4*)(stg + br * 256 + bc8 * 4 + 16);
    const float f[8] = {w0.x, w0.y, w0.z, w0.w, w1.x, w1.y, w1.z, w1.w};
    uint32_t hv[4], lv[4];
#pragma unroll
    for (int j = 0; j < 4; j++) {
        __nv_bfloat162 h = __floats2bfloat162_rn(f[2 * j], f[2 * j + 1]);
        const float r0 = f[2 * j]     - __bfloat162float(h.x);
        const float r1 = f[2 * j + 1] - __bfloat162float(h.y);
        __nv_bfloat162 l = __floats2bfloat162_rn(r0, r1);
        hv[j] = *(uint32_t*)&h;
        lv[j] = *(uint32_t*)&l;
    }
    *(uint4*)(bh + br * B_PITCH + bc8 * 2) = make_uint4(hv[0], hv[1], hv[2], hv[3]);
    *(uint4*)(bl + br * B_PITCH + bc8 * 2) = make_uint4(lv[0], lv[1], lv[2], lv[3]);
}

// ================= init / router =================
__global__ void zero_counts_kernel() {
    if (threadIdx.x < NEXP) g_count[threadIdx.x] = 0;
}

__global__ void router_kernel(const float* __restrict__ x, const float* __restrict__ rw) {
    __shared__ float xs[HDIM];
    __shared__ float aff[NEXP];
    const int t = blockIdx.x;
    const int tid = threadIdx.x; // 64
    for (int h = tid; h < HDIM; h += 64) xs[h] = x[(size_t)t * HDIM + h];
    __syncthreads();
    float acc = 0.f;
#pragma unroll 8
    for (int h = 0; h < HDIM; h++) acc += xs[h] * rw[h * NEXP + tid];
    aff[tid] = 1.f / (1.f + expf(-acc));
    __syncthreads();
    if (tid == 0) {
        float tmp[NEXP];
#pragma unroll
        for (int i = 0; i < NEXP; i++) tmp[i] = aff[i];
        int idx[TOPK]; float sc[TOPK]; float s = 0.f;
        for (int k = 0; k < TOPK; k++) {
            int bi = 0; float bv = -1e30f;
            for (int i = 0; i < NEXP; i++) if (tmp[i] > bv) { bv = tmp[i]; bi = i; }
            idx[k] = bi; sc[k] = bv; tmp[bi] = -1e30f; s += bv;
        }
        const float inv = 1.f / (s + 1e-9f);
        for (int k = 0; k < TOPK; k++) {
            const int e = idx[k];
            const int slot = atomicAdd(&g_count[e], 1);
            g_assign_tok[e * T_TOK + slot] = t;
            g_assign_w[e * T_TOK + slot]   = sc[k] * inv;
            g_tok2slot[t * TOPK + k]       = e * T_TOK + slot;
        }
    }
}

__global__ void splitx_kernel(const float* __restrict__ x) {
    const int i = (blockIdx.x * 256 + threadIdx.x) * 4;
    float4 v = *(const float4*)(x + i);
    float a[4] = {v.x, v.y, v.z, v.w};
    __nv_bfloat162 h01 = __floats2bfloat162_rn(a[0], a[1]);
    __nv_bfloat162 h23 = __floats2bfloat162_rn(a[2], a[3]);
    float l0 = a[0] - __bfloat162float(h01.x);
    float l1 = a[1] - __bfloat162float(h01.y);
    float l2 = a[2] - __bfloat162float(h23.x);
    float l3 = a[3] - __bfloat162float(h23.y);
    __nv_bfloat162 q01 = __floats2bfloat162_rn(l0, l1);
    __nv_bfloat162 q23 = __floats2bfloat162_rn(l2, l3);
    uint2 hv, lv;
    hv.x = *(uint32_t*)&h01; hv.y = *(uint32_t*)&h23;
    lv.x = *(uint32_t*)&q01; lv.y = *(uint32_t*)&q23;
    *(uint2*)(g_xhi + i) = hv;
    *(uint2*)(g_xlo + i) = lv;
}

// ================= fused gate/up GEMM (HMMA, split-bf16, 2-stage cp.async pipeline) ====
__global__ __launch_bounds__(256, 2) void gateup_kernel(
    const float* __restrict__ eg, const float* __restrict__ eu,
    const float* __restrict__ sg, const float* __restrict__ su)
{
    extern __shared__ __align__(16) char dyn[];
    __shared__ int toks[128];

    const int e = blockIdx.z;
    const bool shared_e = (e == NEXP);
    const int n0 = blockIdx.x * 64;
    const int row0 = blockIdx.y * 128;
    const int n = shared_e ? T_TOK : g_count[e];
    if (row0 >= n) return;

    const int tid = threadIdx.x;
    const int wid = tid >> 5, lane = tid & 31;
    const int wm = wid >> 1, wn = wid & 1;

    if (tid < 128) {
        const int r = row0 + tid;
        toks[tid] = shared_e ? r : ((r < n) ? g_assign_tok[e * T_TOK + r] : 0);
    }
    __syncthreads();

    const float* WG = shared_e ? sg : (eg + (size_t)e * HDIM * IDIM);
    const float* WU = shared_e ? su : (eu + (size_t)e * HDIM * IDIM);

    char* stgF = dyn + 2 * GU_STG;          // fp32 staging: gate 8K, up 8K
    const uint32_t uStgG = smem_u32(stgF);
    const uint32_t uStgU = uStgG + 8192;

    // A copy mapping
    const int ar = tid >> 1, ahalf = tid & 1;
    const size_t aBase = (size_t)toks[ar] * HDIM + ahalf * 16;
    const uint32_t aOff = (uint32_t)(ar * A_PITCH + ahalf * 32);
    // B copy mapping
    const int br = tid >> 3, bc8 = (tid & 7) * 8;
    const float* gSrc = WG + (size_t)br * IDIM + n0 + bc8;
    const float* uSrc = WU + (size_t)br * IDIM + n0 + bc8;
    const uint32_t bStgOff = (uint32_t)(br * 256 + bc8 * 4);

    const uint32_t uDyn = smem_u32(dyn);

    // ---- prologue: stage 0 ----
    {
        const uint32_t b0 = uDyn;
        cpa16(b0 + aOff,                    g_xhi + aBase);
        cpa16(b0 + aOff + 16,               g_xhi + aBase + 8);
        cpa16(b0 + A_BYTES + aOff,          g_xlo + aBase);
        cpa16(b0 + A_BYTES + aOff + 16,     g_xlo + aBase + 8);
        cpa16(uStgG + bStgOff,      gSrc);
        cpa16(uStgG + bStgOff + 16, gSrc + 4);
        cpa16(uStgU + bStgOff,      uSrc);
        cpa16(uStgU + bStgOff + 16, uSrc + 4);
        CP_COMMIT();
        CP_WAIT0();
        char* buf0 = dyn;
        convB(stgF,        buf0 + 2 * A_BYTES,              buf0 + 2 * A_BYTES + B_BYTES,     br, bc8);
        convB(stgF + 8192, buf0 + 2 * A_BYTES + 2 * B_BYTES, buf0 + 2 * A_BYTES + 3 * B_BYTES, br, bc8);
        __syncthreads();
    }

    float gacc[2][4][4] = {};
    float uacc[2][4][4] = {};

    for (int s = 0; s < HDIM / 32; s++) {
        char* cur = dyn + (s & 1) * GU_STG;
        char* nxt = dyn + ((s + 1) & 1) * GU_STG;
        const bool more = (s + 1) < HDIM / 32;
        if (more) {
            const int kn = (s + 1) * 32;
            const uint32_t bn = smem_u32(nxt);
            cpa16(bn + aOff,                g_xhi + aBase + kn);
            cpa16(bn + aOff + 16,           g_xhi + aBase + kn + 8);
            cpa16(bn + A_BYTES + aOff,      g_xlo + aBase + kn);
            cpa16(bn + A_BYTES + aOff + 16, g_xlo + aBase + kn + 8);
            const size_t ko = (size_t)kn * IDIM;
            cpa16(uStgG + bStgOff,      gSrc + ko);
            cpa16(uStgG + bStgOff + 16, gSrc + ko + 4);
            cpa16(uStgU + bStgOff,      uSrc + ko);
            cpa16(uStgU + bStgOff + 16, uSrc + ko + 4);
            CP_COMMIT();
        }

        const uint32_t uAh = smem_u32(cur);
        const uint32_t uAl = uAh + A_BYTES;
        const uint32_t uBgh = uAh + 2 * A_BYTES;
        const uint32_t uBgl = uBgh + B_BYTES;
        const uint32_t uBuh = uBgh + 2 * B_BYTES;
        const uint32_t uBul = uBgh + 3 * B_BYTES;

#pragma unroll
        for (int ks = 0; ks < 2; ks++) {
            uint32_t afh[2][4], afl[2][4];
#pragma unroll
            for (int mi = 0; mi < 2; mi++) {
                const uint32_t aoff = (uint32_t)((wm * 32 + mi * 16 + (lane & 15)) * A_PITCH
                                                 + ks * 32 + (lane >> 4) * 16);
                ldsm4(afh[mi], uAh + aoff);
                ldsm4(afl[mi], uAl + aoff);
            }
#pragma unroll
            for (int ni = 0; ni < 4; ni++) {
                const uint32_t boff = (uint32_t)((ks * 16 + (lane & 15)) * B_PITCH
                                                 + (wn * 32 + ni * 8) * 2);
                uint32_t bh[2], bl[2];
                ldsm2t(bh, uBgh + boff);
                ldsm2t(bl, uBgl + boff);
#pragma unroll
                for (int mi = 0; mi < 2; mi++) {
                    mma16816(gacc[mi][ni], afh[mi], bh);
                    mma16816(gacc[mi][ni], afh[mi], bl);
                    mma16816(gacc[mi][ni], afl[mi], bh);
                }
                ldsm2t(bh, uBuh + boff);
                ldsm2t(bl, uBul + boff);
#pragma unroll
                for (int mi = 0; mi < 2; mi++) {
                    mma16816(uacc[mi][ni], afh[mi], bh);
                    mma16816(uacc[mi][ni], afh[mi], bl);
                    mma16816(uacc[mi][ni], afl[mi], bh);
                }
            }
        }

        if (more) {
            CP_WAIT0();
            convB(stgF,        nxt + 2 * A_BYTES,               nxt + 2 * A_BYTES + B_BYTES,     br, bc8);
            convB(stgF + 8192, nxt + 2 * A_BYTES + 2 * B_BYTES, nxt + 2 * A_BYTES + 3 * B_BYTES, br, bc8);
        }
        __syncthreads();
    }

    // epilogue: act = silu(g)*u*w -> bf16 hi/lo
    int nn = n - row0; if (nn > 128) nn = 128;
#pragma unroll
    for (int mi = 0; mi < 2; mi++) {
#pragma unroll
        for (int p = 0; p < 2; p++) {
            const int m = wm * 32 + mi * 16 + (lane >> 2) + p * 8;
            if (m >= nn) continue;
            float w = 1.f;
            __nv_bfloat16 *dh, *dl;
            if (shared_e) {
                dh = g_sact_hi + (size_t)(row0 + m) * IDIM;
                dl = g_sact_lo + (size_t)(row0 + m) * IDIM;
            } else {
                w = g_assign_w[e * T_TOK + row0 + m];
                const size_t slot = (size_t)e * T_TOK + row0 + m;
                dh = g_act_hi + slot * IDIM;
                dl = g_act_lo + slot * IDIM;
            }
            const int ncb = n0 + wn * 32 + (lane & 3) * 2;
#pragma unroll
            for (int ni = 0; ni < 4; ni++) {
                const float g0 = gacc[mi][ni][p * 2 + 0];
                const float g1 = gacc[mi][ni][p * 2 + 1];
                const float u0 = uacc[mi][ni][p * 2 + 0];
                const float u1 = uacc[mi][ni][p * 2 + 1];
                const float a0 = g0 / (1.f + __expf(-g0)) * u0 * w;
                const float a1 = g1 / (1.f + __expf(-g1)) * u1 * w;
                __nv_bfloat162 h = __floats2bfloat162_rn(a0, a1);
                const float l0 = a0 - __bfloat162float(h.x);
                const float l1 = a1 - __bfloat162float(h.y);
                __nv_bfloat162 l = __floats2bfloat162_rn(l0, l1);
                *(uint32_t*)(dh + ncb + ni * 8) = *(uint32_t*)&h;
                *(uint32_t*)(dl + ncb + ni * 8) = *(uint32_t*)&l;
            }
        }
    }
}

// ================= down GEMM (HMMA, split-bf16, 2-stage cp.async pipeline) =========
__global__ __launch_bounds__(256, 3) void down_kernel(
    const float* __restrict__ ed, const float* __restrict__ sd,
    float* __restrict__ out)
{
    extern __shared__ __align__(16) char dyn[];

    const int e = blockIdx.z;
    const bool shared_e = (e == NEXP);
    const int n0 = blockIdx.x * 64;
    const int row0 = blockIdx.y * 128;
    const int n = shared_e ? T_TOK : g_count[e];
    if (row0 >= n) return;

    const int tid = threadIdx.x;
    const int wid = tid >> 5, lane = tid & 31;
    const int wm = wid >> 1, wn = wid & 1;

    const float* W = shared_e ? sd : (ed + (size_t)e * IDIM * HDIM);
    const __nv_bfloat16* Ah = shared_e ? (g_sact_hi + (size_t)row0 * IDIM)
                                       : (g_act_hi + ((size_t)e * T_TOK + row0) * IDIM);
    const __nv_bfloat16* Al = shared_e ? (g_sact_lo + (size_t)row0 * IDIM)
                                       : (g_act_lo + ((size_t)e * T_TOK + row0) * IDIM);

    char* stgF = dyn + 2 * DN_STG;
    const uint32_t uStg = smem_u32(stgF);

    const int ar = tid >> 1, ahalf = tid & 1;
    const size_t aBase = (size_t)ar * IDIM + ahalf * 16;
    const uint32_t aOff = (uint32_t)(ar * A_PITCH + ahalf * 32);
    const int br = tid >> 3, bc8 = (tid & 7) * 8;
    const float* bSrc = W + (size_t)br * HDIM + n0 + bc8;
    const uint32_t bStgOff = (uint32_t)(br * 256 + bc8 * 4);

    const uint32_t uDyn = smem_u32(dyn);

    // ---- prologue ----
    {
        cpa16(uDyn + aOff,                Ah + aBase);
        cpa16(uDyn + aOff + 16,           Ah + aBase + 8);
        cpa16(uDyn + A_BYTES + aOff,      Al + aBase);
        cpa16(uDyn + A_BYTES + aOff + 16, Al + aBase + 8);
        cpa16(uStg + bStgOff,      bSrc);
        cpa16(uStg + bStgOff + 16, bSrc + 4);
        CP_COMMIT();
        CP_WAIT0();
        convB(stgF, dyn + 2 * A_BYTES, dyn + 2 * A_BYTES + B_BYTES, br, bc8);
        __syncthreads();
    }

    float acc[2][4][4] = {};

    for (int s = 0; s < IDIM / 32; s++) {
        char* cur = dyn + (s & 1) * DN_STG;
        char* nxt = dyn + ((s + 1) & 1) * DN_STG;
        const bool more = (s + 1) < IDIM / 32;
        if (more) {
            const int kn = (s + 1) * 32;
            const uint32_t bn = smem_u32(nxt);
            cpa16(bn + aOff,                Ah + aBase + kn);
            cpa16(bn + aOff + 16,           Ah + aBase + kn + 8);
            cpa16(bn + A_BYTES + aOff,      Al + aBase + kn);
            cpa16(bn + A_BYTES + aOff + 16, Al + aBase + kn + 8);
            const size_t ko = (size_t)kn * HDIM;
            cpa16(uStg + bStgOff,      bSrc + ko);
            cpa16(uStg + bStgOff + 16, bSrc + ko + 4);
            CP_COMMIT();
        }

        const uint32_t uAh = smem_u32(cur);
        const uint32_t uAl = uAh + A_BYTES;
        const uint32_t uBh = uAh + 2 * A_BYTES;
        const uint32_t uBl = uBh + B_BYTES;

#pragma unroll
        for (int ks = 0; ks < 2; ks++) {
            uint32_t afh[2][4], afl[2][4];
#pragma unroll
            for (int mi = 0; mi < 2; mi++) {
                const uint32_t aoff = (uint32_t)((wm * 32 + mi * 16 + (lane & 15)) * A_PITCH
                                                 + ks * 32 + (lane >> 4) * 16);
                ldsm4(afh[mi], uAh + aoff);
                ldsm4(afl[mi], uAl + aoff);
            }
#pragma unroll
            for (int ni = 0; ni < 4; ni++) {
                const uint32_t boff = (uint32_t)((ks * 16 + (lane & 15)) * B_PITCH
                                                 + (wn * 32 + ni * 8) * 2);
                uint32_t bh[2], bl[2];
                ldsm2t(bh, uBh + boff);
                ldsm2t(bl, uBl + boff);
#pragma unroll
                for (int mi = 0; mi < 2; mi++) {
                    mma16816(acc[mi][ni], afh[mi], bh);
                    mma16816(acc[mi][ni], afh[mi], bl);
                    mma16816(acc[mi][ni], afl[mi], bh);
                }
            }
        }

        if (more) {
            CP_WAIT0();
            convB(stgF, nxt + 2 * A_BYTES, nxt + 2 * A_BYTES + B_BYTES, br, bc8);
        }
        __syncthreads();
    }

#pragma unroll
    for (int mi = 0; mi < 2; mi++) {
#pragma unroll
        for (int p = 0; p < 2; p++) {
            const int m = wm * 32 + mi * 16 + (lane >> 2) + p * 8;
            float* dst = shared_e ? (out + (size_t)(row0 + m) * HDIM)
                                  : (g_part + ((size_t)e * T_TOK + row0 + m) * HDIM);
            const int ncb = n0 + wn * 32 + (lane & 3) * 2;
#pragma unroll
            for (int ni = 0; ni < 4; ni++) {
                float2 o = make_float2(acc[mi][ni][p * 2 + 0], acc[mi][ni][p * 2 + 1]);
                *(float2*)(dst + ncb + ni * 8) = o;
            }
        }
    }
}

// ================= gather =================
__global__ void gather_kernel(float* __restrict__ out) {
    __shared__ int slots[TOPK];
    const int t = blockIdx.x;
    if (threadIdx.x < TOPK) slots[threadIdx.x] = g_tok2slot[t * TOPK + threadIdx.x];
    __syncthreads();
    const int h = threadIdx.x * 4;
    float4 acc = *(float4*)(out + (size_t)t * HDIM + h);
#pragma unroll
    for (int k = 0; k < TOPK; k++) {
        const float4 p = *(const float4*)(g_part + (size_t)slots[k] * HDIM + h);
        acc.x += p.x; acc.y += p.y; acc.z += p.z; acc.w += p.w;
    }
    *(float4*)(out + (size_t)t * HDIM + h) = acc;
}

// ================= launch =================
extern "C" void kernel_launch(void* const* d_in, const int* in_sizes, int n_in,
                              void* d_out, int out_size) {
    const float* x  = (const float*)d_in[0];
    const float* rw = (const float*)d_in[1];
    const float* sg = (const float*)d_in[2];
    const float* su = (const float*)d_in[3];
    const float* sd = (const float*)d_in[4];
    const float* eg = (const float*)d_in[5];
    const float* eu = (const float*)d_in[6];
    const float* ed = (const float*)d_in[7];
    float* out = (float*)d_out;

    cudaFuncSetAttribute(gateup_kernel, cudaFuncAttributeMaxDynamicSharedMemorySize, GU_SMEM);
    cudaFuncSetAttribute(down_kernel,   cudaFuncAttributeMaxDynamicSharedMemorySize, DN_SMEM);

    zero_counts_kernel<<<1, 64>>>();
    router_kernel<<<T_TOK, 64>>>(x, rw);
    splitx_kernel<<<1024, 256>>>(x);
    gateup_kernel<<<dim3(IDIM / 64, T_TOK / 128, NEXP + 1), 256, GU_SMEM>>>(eg, eu, sg, su);
    down_kernel<<<dim3(HDIM / 64, T_TOK / 128, NEXP + 1), 256, DN_SMEM>>>(ed, sd, out);
    gather_kernel<<<T_TOK, 256>>>(out);
}

// round 5
// speedup vs baseline: 1.1651x; 1.1651x over previous
#include <cuda_runtime.h>
#include <cuda_bf16.h>
#include <math.h>
#include <stdint.h>

#define T_TOK 1024
#define HDIM  1024
#define IDIM  512
#define NEXP  64
#define TOPK  8

// ================= scratch (static device globals; no allocation) =================
__device__ int   g_count[NEXP];
__device__ int   g_assign_tok[NEXP * T_TOK];
__device__ float g_assign_w[NEXP * T_TOK];
__device__ int   g_tok2slot[T_TOK * TOPK];
__device__ __nv_bfloat16 g_xhi[T_TOK * HDIM];
__device__ __nv_bfloat16 g_xlo[T_TOK * HDIM];
__device__ __nv_bfloat16 g_sact_hi[T_TOK * IDIM];
__device__ __nv_bfloat16 g_sact_lo[T_TOK * IDIM];
__device__ __nv_bfloat16 g_act_hi[(size_t)NEXP * T_TOK * IDIM];
__device__ __nv_bfloat16 g_act_lo[(size_t)NEXP * T_TOK * IDIM];
__device__ float g_part[(size_t)NEXP * T_TOK * HDIM];

// ================= primitives =================
__device__ __forceinline__ uint32_t smem_u32(const void* p) {
    uint32_t a;
    asm("{ .reg .u64 t; cvta.to.shared.u64 t, %1; cvt.u32.u64 %0, t; }" : "=r"(a) : "l"(p));
    return a;
}
__device__ __forceinline__ void ldsm4(uint32_t* r, uint32_t a) {
    asm volatile("ldmatrix.sync.aligned.m8n8.x4.shared.b16 {%0,%1,%2,%3}, [%4];"
                 : "=r"(r[0]), "=r"(r[1]), "=r"(r[2]), "=r"(r[3]) : "r"(a));
}
__device__ __forceinline__ void ldsm4t(uint32_t* r, uint32_t a) {
    asm volatile("ldmatrix.sync.aligned.m8n8.x4.trans.shared.b16 {%0,%1,%2,%3}, [%4];"
                 : "=r"(r[0]), "=r"(r[1]), "=r"(r[2]), "=r"(r[3]) : "r"(a));
}
__device__ __forceinline__ void mma16816(float* c, const uint32_t* a, const uint32_t* b) {
    asm volatile(
        "mma.sync.aligned.m16n8k16.row.col.f32.bf16.bf16.f32 "
        "{%0,%1,%2,%3}, {%4,%5,%6,%7}, {%8,%9}, {%0,%1,%2,%3};"
        : "+f"(c[0]), "+f"(c[1]), "+f"(c[2]), "+f"(c[3])
        : "r"(a[0]), "r"(a[1]), "r"(a[2]), "r"(a[3]), "r"(b[0]), "r"(b[1]));
}
__device__ __forceinline__ void cpa16(uint32_t dst, const void* src) {
    asm volatile("cp.async.ca.shared.global [%0], [%1], 16;" :: "r"(dst), "l"(src));
}
#define CP_COMMIT() asm volatile("cp.async.commit_group;" ::: "memory")
#define CP_WAIT0()  asm volatile("cp.async.wait_group 0;"  ::: "memory")

// ================= layout (K-stage = 64) =================
#define PITCH   144                       // 64 bf16 (128B) + 16B pad
#define A_BYTES (128 * PITCH)             // 18432 (one of hi/lo)
#define B_BYTES (64 * PITCH)              // 9216  (one of hi/lo)
#define GU_SMEM (2 * A_BYTES + 4 * B_BYTES)   // 73728
#define DN_SMEM (2 * A_BYTES + 2 * B_BYTES)   // 55296

// B stage: W[k0..k0+64)[n0..n0+64) fp32 -> bf16 hi/lo smem [k][n]
// thread: row r = tid>>2 (64 rows), cols c16 = (tid&3)*16
__device__ __forceinline__ void stage_b64(const float* __restrict__ src, int ld,
                                          char* bh, char* bl, int r, int c16) {
    float f[16];
#pragma unroll
    for (int q = 0; q < 4; q++) {
        const float4 v = *(const float4*)(src + (size_t)r * ld + c16 + q * 4);
        f[q * 4 + 0] = v.x; f[q * 4 + 1] = v.y; f[q * 4 + 2] = v.z; f[q * 4 + 3] = v.w;
    }
    uint32_t hv[8], lv[8];
#pragma unroll
    for (int j = 0; j < 8; j++) {
        __nv_bfloat162 h = __floats2bfloat162_rn(f[2 * j], f[2 * j + 1]);
        const float r0 = f[2 * j]     - __bfloat162float(h.x);
        const float r1 = f[2 * j + 1] - __bfloat162float(h.y);
        __nv_bfloat162 l = __floats2bfloat162_rn(r0, r1);
        hv[j] = *(uint32_t*)&h;
        lv[j] = *(uint32_t*)&l;
    }
    const int off = r * PITCH + c16 * 2;
    *(uint4*)(bh + off)      = make_uint4(hv[0], hv[1], hv[2], hv[3]);
    *(uint4*)(bh + off + 16) = make_uint4(hv[4], hv[5], hv[6], hv[7]);
    *(uint4*)(bl + off)      = make_uint4(lv[0], lv[1], lv[2], lv[3]);
    *(uint4*)(bl + off + 16) = make_uint4(lv[4], lv[5], lv[6], lv[7]);
}

// ================= init / router =================
__global__ void zero_counts_kernel() {
    if (threadIdx.x < NEXP) g_count[threadIdx.x] = 0;
}

__global__ void router_kernel(const float* __restrict__ x, const float* __restrict__ rw) {
    __shared__ float xs[HDIM];
    __shared__ float aff[NEXP];
    const int t = blockIdx.x;
    const int tid = threadIdx.x; // 64
    for (int h = tid; h < HDIM; h += 64) xs[h] = x[(size_t)t * HDIM + h];
    __syncthreads();
    float acc = 0.f;
#pragma unroll 8
    for (int h = 0; h < HDIM; h++) acc += xs[h] * rw[h * NEXP + tid];
    aff[tid] = 1.f / (1.f + expf(-acc));
    __syncthreads();
    if (tid == 0) {
        float tmp[NEXP];
#pragma unroll
        for (int i = 0; i < NEXP; i++) tmp[i] = aff[i];
        int idx[TOPK]; float sc[TOPK]; float s = 0.f;
        for (int k = 0; k < TOPK; k++) {
            int bi = 0; float bv = -1e30f;
            for (int i = 0; i < NEXP; i++) if (tmp[i] > bv) { bv = tmp[i]; bi = i; }
            idx[k] = bi; sc[k] = bv; tmp[bi] = -1e30f; s += bv;
        }
        const float inv = 1.f / (s + 1e-9f);
        for (int k = 0; k < TOPK; k++) {
            const int e = idx[k];
            const int slot = atomicAdd(&g_count[e], 1);
            g_assign_tok[e * T_TOK + slot] = t;
            g_assign_w[e * T_TOK + slot]   = sc[k] * inv;
            g_tok2slot[t * TOPK + k]       = e * T_TOK + slot;
        }
    }
}

__global__ void splitx_kernel(const float* __restrict__ x) {
    const int i = (blockIdx.x * 256 + threadIdx.x) * 4;
    float4 v = *(const float4*)(x + i);
    float a[4] = {v.x, v.y, v.z, v.w};
    __nv_bfloat162 h01 = __floats2bfloat162_rn(a[0], a[1]);
    __nv_bfloat162 h23 = __floats2bfloat162_rn(a[2], a[3]);
    float l0 = a[0] - __bfloat162float(h01.x);
    float l1 = a[1] - __bfloat162float(h01.y);
    float l2 = a[2] - __bfloat162float(h23.x);
    float l3 = a[3] - __bfloat162float(h23.y);
    __nv_bfloat162 q01 = __floats2bfloat162_rn(l0, l1);
    __nv_bfloat162 q23 = __floats2bfloat162_rn(l2, l3);
    uint2 hv, lv;
    hv.x = *(uint32_t*)&h01; hv.y = *(uint32_t*)&h23;
    lv.x = *(uint32_t*)&q01; lv.y = *(uint32_t*)&q23;
    *(uint2*)(g_xhi + i) = hv;
    *(uint2*)(g_xlo + i) = lv;
}

// ================= fused gate/up GEMM (HMMA, split-bf16 3-pass, K-stage 64) =========
__global__ __launch_bounds__(256, 2) void gateup_kernel(
    const float* __restrict__ eg, const float* __restrict__ eu,
    const float* __restrict__ sg, const float* __restrict__ su)
{
    extern __shared__ __align__(16) char dyn[];
    __shared__ int toks[128];

    const int e = blockIdx.z;
    const bool shared_e = (e == NEXP);
    const int n0 = blockIdx.x * 64;
    const int row0 = blockIdx.y * 128;
    const int n = shared_e ? T_TOK : g_count[e];
    if (row0 >= n) return;

    const int tid = threadIdx.x;
    const int wid = tid >> 5, lane = tid & 31;
    const int wm = wid >> 1, wn = wid & 1;

    if (tid < 128) {
        const int r = row0 + tid;
        toks[tid] = shared_e ? r : ((r < n) ? g_assign_tok[e * T_TOK + r] : 0);
    }
    __syncthreads();

    const float* WG = shared_e ? sg : (eg + (size_t)e * HDIM * IDIM);
    const float* WU = shared_e ? su : (eu + (size_t)e * HDIM * IDIM);

    char* sAh = dyn;
    char* sAl = dyn + A_BYTES;
    char* sBgh = dyn + 2 * A_BYTES;
    char* sBgl = sBgh + B_BYTES;
    char* sBuh = sBgh + 2 * B_BYTES;
    char* sBul = sBgh + 3 * B_BYTES;
    const uint32_t uAh = smem_u32(sAh), uAl = uAh + A_BYTES;
    const uint32_t uBg = uAh + 2 * A_BYTES;
    const uint32_t uBu = uBg + 2 * B_BYTES;

    // A copy mapping: row = tid>>1 (128), seg = (tid&1)*64B
    const int arow = tid >> 1, aseg = tid & 1;
    const size_t aBase = (size_t)toks[arow] * HDIM + aseg * 32;
    const uint32_t aDst = (uint32_t)(arow * PITCH + aseg * 64);
    // B mapping: r = tid>>2 (64), c16 = (tid&3)*16
    const int br = tid >> 2, bc16 = (tid & 3) * 16;
    const float* gSrc = WG + n0;
    const float* uSrc = WU + n0;

    float gacc[2][4][4] = {};
    float uacc[2][4][4] = {};

    for (int s = 0; s < HDIM / 64; s++) {
        const int k0 = s * 64;
        // A: async copies (L1-allocating), overlap with B load+convert
        {
            const size_t ab = aBase + k0;
#pragma unroll
            for (int q = 0; q < 4; q++) {
                cpa16(uAh + aDst + q * 16, g_xhi + ab + q * 8);
                cpa16(uAl + aDst + q * 16, g_xlo + ab + q * 8);
            }
            CP_COMMIT();
        }
        // B: LDG -> convert -> STS (register path)
        stage_b64(gSrc + (size_t)k0 * IDIM, IDIM, sBgh, sBgl, br, bc16);
        stage_b64(uSrc + (size_t)k0 * IDIM, IDIM, sBuh, sBul, br, bc16);
        CP_WAIT0();
        __syncthreads();

#pragma unroll
        for (int ks = 0; ks < 4; ks++) {
            uint32_t afh[2][4], afl[2][4];
#pragma unroll
            for (int mi = 0; mi < 2; mi++) {
                const uint32_t aoff = (uint32_t)((wm * 32 + mi * 16 + (lane & 15)) * PITCH
                                                 + ks * 32 + (lane >> 4) * 16);
                ldsm4(afh[mi], uAh + aoff);
                ldsm4(afl[mi], uAl + aoff);
            }
#pragma unroll
            for (int p = 0; p < 2; p++) {
                const uint32_t boff = (uint32_t)((ks * 16 + (lane & 15)) * PITCH
                                                 + (wn * 32 + p * 16 + (lane >> 4) * 8) * 2);
                uint32_t bh[4], bl[4];
                ldsm4t(bh, uBg + boff);
                ldsm4t(bl, uBg + B_BYTES + boff);
#pragma unroll
                for (int mi = 0; mi < 2; mi++) {
                    mma16816(gacc[mi][2 * p],     afh[mi], bh);
                    mma16816(gacc[mi][2 * p],     afh[mi], bl);
                    mma16816(gacc[mi][2 * p],     afl[mi], bh);
                    mma16816(gacc[mi][2 * p + 1], afh[mi], bh + 2);
                    mma16816(gacc[mi][2 * p + 1], afh[mi], bl + 2);
                    mma16816(gacc[mi][2 * p + 1], afl[mi], bh + 2);
                }
                ldsm4t(bh, uBu + boff);
                ldsm4t(bl, uBu + B_BYTES + boff);
#pragma unroll
                for (int mi = 0; mi < 2; mi++) {
                    mma16816(uacc[mi][2 * p],     afh[mi], bh);
                    mma16816(uacc[mi][2 * p],     afh[mi], bl);
                    mma16816(uacc[mi][2 * p],     afl[mi], bh);
                    mma16816(uacc[mi][2 * p + 1], afh[mi], bh + 2);
                    mma16816(uacc[mi][2 * p + 1], afh[mi], bl + 2);
                    mma16816(uacc[mi][2 * p + 1], afl[mi], bh + 2);
                }
            }
        }
        __syncthreads();
    }

    // epilogue: act = silu(g)*u*w -> bf16 hi/lo
    int nn = n - row0; if (nn > 128) nn = 128;
#pragma unroll
    for (int mi = 0; mi < 2; mi++) {
#pragma unroll
        for (int p = 0; p < 2; p++) {
            const int m = wm * 32 + mi * 16 + (lane >> 2) + p * 8;
            if (m >= nn) continue;
            float w = 1.f;
            __nv_bfloat16 *dh, *dl;
            if (shared_e) {
                dh = g_sact_hi + (size_t)(row0 + m) * IDIM;
                dl = g_sact_lo + (size_t)(row0 + m) * IDIM;
            } else {
                w = g_assign_w[e * T_TOK + row0 + m];
                const size_t slot = (size_t)e * T_TOK + row0 + m;
                dh = g_act_hi + slot * IDIM;
                dl = g_act_lo + slot * IDIM;
            }
            const int ncb = n0 + wn * 32 + (lane & 3) * 2;
#pragma unroll
            for (int ni = 0; ni < 4; ni++) {
                const float g0 = gacc[mi][ni][p * 2 + 0];
                const float g1 = gacc[mi][ni][p * 2 + 1];
                const float u0 = uacc[mi][ni][p * 2 + 0];
                const float u1 = uacc[mi][ni][p * 2 + 1];
                const float a0 = g0 / (1.f + __expf(-g0)) * u0 * w;
                const float a1 = g1 / (1.f + __expf(-g1)) * u1 * w;
                __nv_bfloat162 h = __floats2bfloat162_rn(a0, a1);
                const float l0 = a0 - __bfloat162float(h.x);
                const float l1 = a1 - __bfloat162float(h.y);
                __nv_bfloat162 l = __floats2bfloat162_rn(l0, l1);
                *(uint32_t*)(dh + ncb + ni * 8) = *(uint32_t*)&h;
                *(uint32_t*)(dl + ncb + ni * 8) = *(uint32_t*)&l;
            }
        }
    }
}

// ================= down GEMM (HMMA, split-bf16 3-pass, K-stage 64) =========
__global__ __launch_bounds__(256, 2) void down_kernel(
    const float* __restrict__ ed, const float* __restrict__ sd,
    float* __restrict__ out)
{
    extern __shared__ __align__(16) char dyn[];

    const int e = blockIdx.z;
    const bool shared_e = (e == NEXP);
    const int n0 = blockIdx.x * 64;
    const int row0 = blockIdx.y * 128;
    const int n = shared_e ? T_TOK : g_count[e];
    if (row0 >= n) return;

    const int tid = threadIdx.x;
    const int wid = tid >> 5, lane = tid & 31;
    const int wm = wid >> 1, wn = wid & 1;

    const float* W = shared_e ? sd : (ed + (size_t)e * IDIM * HDIM);
    const __nv_bfloat16* Ahp = shared_e ? (g_sact_hi + (size_t)row0 * IDIM)
                                        : (g_act_hi + ((size_t)e * T_TOK + row0) * IDIM);
    const __nv_bfloat16* Alp = shared_e ? (g_sact_lo + (size_t)row0 * IDIM)
                                        : (g_act_lo + ((size_t)e * T_TOK + row0) * IDIM);

    char* sAh = dyn;
    char* sAl = dyn + A_BYTES;
    char* sBh = dyn + 2 * A_BYTES;
    char* sBl = sBh + B_BYTES;
    const uint32_t uAh = smem_u32(sAh), uAl = uAh + A_BYTES;
    const uint32_t uB = uAh + 2 * A_BYTES;

    const int arow = tid >> 1, aseg = tid & 1;
    const size_t aBase = (size_t)arow * IDIM + aseg * 32;
    const uint32_t aDst = (uint32_t)(arow * PITCH + aseg * 64);
    const int br = tid >> 2, bc16 = (tid & 3) * 16;
    const float* bSrc = W + n0;

    float acc[2][4][4] = {};

    for (int s = 0; s < IDIM / 64; s++) {
        const int k0 = s * 64;
        {
            const size_t ab = aBase + k0;
#pragma unroll
            for (int q = 0; q < 4; q++) {
                cpa16(uAh + aDst + q * 16, Ahp + ab + q * 8);
                cpa16(uAl + aDst + q * 16, Alp + ab + q * 8);
            }
            CP_COMMIT();
        }
        stage_b64(bSrc + (size_t)k0 * HDIM, HDIM, sBh, sBl, br, bc16);
        CP_WAIT0();
        __syncthreads();

#pragma unroll
        for (int ks = 0; ks < 4; ks++) {
            uint32_t afh[2][4], afl[2][4];
#pragma unroll
            for (int mi = 0; mi < 2; mi++) {
                const uint32_t aoff = (uint32_t)((wm * 32 + mi * 16 + (lane & 15)) * PITCH
                                                 + ks * 32 + (lane >> 4) * 16);
                ldsm4(afh[mi], uAh + aoff);
                ldsm4(afl[mi], uAl + aoff);
            }
#pragma unroll
            for (int p = 0; p < 2; p++) {
                const uint32_t boff = (uint32_t)((ks * 16 + (lane & 15)) * PITCH
                                                 + (wn * 32 + p * 16 + (lane >> 4) * 8) * 2);
                uint32_t bh[4], bl[4];
                ldsm4t(bh, uB + boff);
                ldsm4t(bl, uB + B_BYTES + boff);
#pragma unroll
                for (int mi = 0; mi < 2; mi++) {
                    mma16816(acc[mi][2 * p],     afh[mi], bh);
                    mma16816(acc[mi][2 * p],     afh[mi], bl);
                    mma16816(acc[mi][2 * p],     afl[mi], bh);
                    mma16816(acc[mi][2 * p + 1], afh[mi], bh + 2);
                    mma16816(acc[mi][2 * p + 1], afh[mi], bl + 2);
                    mma16816(acc[mi][2 * p + 1], afl[mi], bh + 2);
                }
            }
        }
        __syncthreads();
    }

#pragma unroll
    for (int mi = 0; mi < 2; mi++) {
#pragma unroll
        for (int p = 0; p < 2; p++) {
            const int m = wm * 32 + mi * 16 + (lane >> 2) + p * 8;
            float* dst = shared_e ? (out + (size_t)(row0 + m) * HDIM)
                                  : (g_part + ((size_t)e * T_TOK + row0 + m) * HDIM);
            const int ncb = n0 + wn * 32 + (lane & 3) * 2;
#pragma unroll
            for (int ni = 0; ni < 4; ni++) {
                float2 o = make_float2(acc[mi][ni][p * 2 + 0], acc[mi][ni][p * 2 + 1]);
                *(float2*)(dst + ncb + ni * 8) = o;
            }
        }
    }
}

// ================= gather =================
__global__ void gather_kernel(float* __restrict__ out) {
    __shared__ int slots[TOPK];
    const int t = blockIdx.x;
    if (threadIdx.x < TOPK) slots[threadIdx.x] = g_tok2slot[t * TOPK + threadIdx.x];
    __syncthreads();
    const int h = threadIdx.x * 4;
    float4 acc = *(float4*)(out + (size_t)t * HDIM + h);
#pragma unroll
    for (int k = 0; k < TOPK; k++) {
        const float4 p = *(const float4*)(g_part + (size_t)slots[k] * HDIM + h);
        acc.x += p.x; acc.y += p.y; acc.z += p.z; acc.w += p.w;
    }
    *(float4*)(out + (size_t)t * HDIM + h) = acc;
}

// ================= launch =================
extern "C" void kernel_launch(void* const* d_in, const int* in_sizes, int n_in,
                              void* d_out, int out_size) {
    const float* x  = (const float*)d_in[0];
    const float* rw = (const float*)d_in[1];
    const float* sg = (const float*)d_in[2];
    const float* su = (const float*)d_in[3];
    const float* sd = (const float*)d_in[4];
    const float* eg = (const float*)d_in[5];
    const float* eu = (const float*)d_in[6];
    const float* ed = (const float*)d_in[7];
    float* out = (float*)d_out;

    cudaFuncSetAttribute(gateup_kernel, cudaFuncAttributeMaxDynamicSharedMemorySize, GU_SMEM);
    cudaFuncSetAttribute(down_kernel,   cudaFuncAttributeMaxDynamicSharedMemorySize, DN_SMEM);

    zero_counts_kernel<<<1, 64>>>();
    router_kernel<<<T_TOK, 64>>>(x, rw);
    splitx_kernel<<<1024, 256>>>(x);
    gateup_kernel<<<dim3(IDIM / 64, T_TOK / 128, NEXP + 1), 256, GU_SMEM>>>(eg, eu, sg, su);
    down_kernel<<<dim3(HDIM / 64, T_TOK / 128, NEXP + 1), 256, DN_SMEM>>>(ed, sd, out);
    gather_kernel<<<T_TOK, 256>>>(out);
}